// round 14
// baseline (speedup 1.0000x reference)
#include <cuda_runtime.h>
#include <math.h>

// ---------------- problem constants ----------------
#define NPTS 43750
#define NROW 175
#define KTOK 250

#define S0A 56
#define S0B 350
#define S0C 512
#define S1A 28
#define S1B 175
#define S1C 256
#define S2A 14
#define S2B 88
#define S2C 128

#define CAP1 350000
#define CAP2 69000

#define L0VOX (S0A*S0B*S0C)   // 10,035,200
#define L1VOX (S1A*S1B*S1C)   // 1,254,400
#define L2VOX (S2A*S2B*S2C)   // 157,696

// ---------------- scratch (static device globals; no allocation) ----------------
__device__ float g_fatt[NPTS];
__device__ float g_f0[NPTS*16];
__device__ int g_lut0[L0VOX];
__device__ unsigned char g_om1[L1VOX];
__device__ int g_lut1[L1VOX];
__device__ int g_oc1[CAP1];
__device__ unsigned char g_om2[L2VOX];
__device__ int g_lut2[L2VOX];
__device__ int g_oc2[CAP2];
__device__ int g_cnt[2];
__device__ float g_f1a[CAP1*32];
__device__ float g_f1b[CAP1*32];
__device__ float g_f2a[CAP2*128];
__device__ float g_f2b[CAP2*128];

// ---------------- attention (per radar row, 4 layers) ----------------
__global__ void __launch_bounds__(256) attn_kernel(
    const float* __restrict__ vf, const int* __restrict__ coors,
    const float* __restrict__ ele_t, const float* __restrict__ azi_t,
    const float* __restrict__ wq, const float* __restrict__ bq,
    const float* __restrict__ wk, const float* __restrict__ bk,
    const float* __restrict__ wv, const float* __restrict__ bv)
{
    __shared__ float sx[KTOK];
    __shared__ float sea[KTOK][6];
    __shared__ float sk[KTOK][32];
    __shared__ float sv[KTOK];

    const int r = blockIdx.x;
    const int tid = threadIdx.x;
    const int j = tid;

    if (j < KTOK) {
        int i = r*KTOK + j;
        sx[j] = log10f(vf[2*i]);           // voxel_features[:, -2] == col 0
        int c1 = coors[4*i+1], c3 = coors[4*i+3];
        sea[j][0]=ele_t[c1*3+0]; sea[j][1]=ele_t[c1*3+1]; sea[j][2]=ele_t[c1*3+2];
        sea[j][3]=azi_t[c3*3+0]; sea[j][4]=azi_t[c3*3+1]; sea[j][5]=azi_t[c3*3+2];
    }
    __syncthreads();

    const float scale = 0.17677669529663687f;  // 32^-0.5

    for (int l = 0; l < 4; l++) {
        // K projection (cooperative)
        for (int t = tid; t < KTOK*32; t += 256) {
            int jj = t >> 5, d = t & 31;
            const float* w = wk + l*7*32 + d;
            float acc = bk[l*32+d] + sx[jj]*w[0];
            #pragma unroll
            for (int u = 0; u < 6; u++) acc += sea[jj][u]*w[(u+1)*32];
            sk[jj][d] = acc;
        }
        // V projection (cooperative)
        for (int t = tid; t < KTOK; t += 256) {
            const float* w = wv + l*7;
            float acc = bv[l] + sx[t]*w[0];
            #pragma unroll
            for (int u = 0; u < 6; u++) acc += sea[t][u]*w[u+1];
            sv[t] = acc;
        }
        __syncthreads();

        float xn = 0.f;
        if (j < KTOK) {
            // Q for own token in registers
            float q[32];
            #pragma unroll
            for (int d = 0; d < 32; d++) {
                const float* w = wq + l*7*32 + d;
                float acc = bq[l*32+d] + sx[j]*w[0];
                #pragma unroll
                for (int u = 0; u < 6; u++) acc += sea[j][u]*w[(u+1)*32];
                q[d] = acc;
            }
            // online softmax over 250 keys
            float m = -1e30f, s = 0.f, a = 0.f;
            for (int jj = 0; jj < KTOK; jj++) {
                float dot = 0.f;
                #pragma unroll
                for (int d = 0; d < 32; d++) dot += q[d]*sk[jj][d];
                dot *= scale;
                float nm = fmaxf(m, dot);
                float corr = expf(m - nm);
                float p = expf(dot - nm);
                s = s*corr + p;
                a = a*corr + p*sv[jj];
                m = nm;
            }
            xn = a / s;
        }
        __syncthreads();
        if (j < KTOK) sx[j] = xn;
        __syncthreads();
    }
    if (j < KTOK) g_fatt[r*KTOK + j] = sx[j];
}

// ---------------- per-point: stem MLP + GN(8) + relu, build lut0, mark om1 ----------------
__global__ void point_kernel(const int* __restrict__ coors,
                             const float* __restrict__ w_in, const float* __restrict__ b_in,
                             const float* __restrict__ gg, const float* __restrict__ gb)
{
    int i = blockIdx.x*blockDim.x + threadIdx.x;
    if (i >= NPTS) return;
    int c1 = coors[4*i+1], c2 = coors[4*i+2], c3 = coors[4*i+3];
    int ele = 2*c1-9, rng = 2*c2, azi = 2*c3+149;
    float f[4] = {(float)ele, (float)rng, (float)azi, g_fatt[i]};
    float y[16];
    #pragma unroll
    for (int c = 0; c < 16; c++) {
        float acc = b_in[c];
        #pragma unroll
        for (int t = 0; t < 4; t++) acc += f[t]*w_in[t*16+c];
        y[c] = acc;
    }
    #pragma unroll
    for (int g = 0; g < 8; g++) {
        float a = y[2*g], b = y[2*g+1];
        float m = 0.5f*(a+b);
        float va = 0.5f*((a-m)*(a-m)+(b-m)*(b-m));
        float rr = rsqrtf(va + 1e-5f);
        float o0 = (a-m)*rr*gg[2*g]   + gb[2*g];
        float o1 = (b-m)*rr*gg[2*g+1] + gb[2*g+1];
        g_f0[i*16+2*g]   = fmaxf(o0, 0.f);
        g_f0[i*16+2*g+1] = fmaxf(o1, 0.f);
    }
    int vox = (ele*S0B + rng)*S0C + azi;
    atomicMax(&g_lut0[vox], i);           // last-wins for duplicate coords
    // downsample mask marks (ele odd, rng even, azi odd)
    int o0a = (ele-1)>>1;
    int o1  = rng>>1;
    int o2a = (azi-1)>>1;
    #pragma unroll
    for (int d0 = 0; d0 < 2; d0++) {
        int o0 = o0a + d0; if (o0 < 0 || o0 >= S1A) continue;
        #pragma unroll
        for (int d2 = 0; d2 < 2; d2++) {
            int o2 = o2a + d2; if (o2 < 0 || o2 >= S1C) continue;
            g_om1[(o0*S1B + o1)*S1C + o2] = 1;
        }
    }
}

// ---------------- compact active voxels -> (oc list, lut, count) ----------------
__global__ void compact_kernel(const unsigned char* __restrict__ om, int* lut, int* oc,
                               int* cnt, int nvox, int cap)
{
    int v = blockIdx.x*blockDim.x + threadIdx.x;
    bool act = (v < nvox) && om[v];
    __shared__ int s_base, s_cnt;
    if (threadIdx.x == 0) s_cnt = 0;
    __syncthreads();
    int r = 0;
    if (act) r = atomicAdd(&s_cnt, 1);
    __syncthreads();
    if (threadIdx.x == 0) s_base = s_cnt ? atomicAdd(cnt, s_cnt) : 0;
    __syncthreads();
    if (act) {
        int pos = s_base + r;
        if (pos < cap) { oc[pos] = v; lut[v] = pos; }
    }
}

// ---------------- mark level-2 downsample mask from oc1 ----------------
__global__ void mark2_kernel()
{
    int i = blockIdx.x*blockDim.x + threadIdx.x;
    if (i >= g_cnt[0]) return;
    int vox = g_oc1[i];
    int c = vox % S1C; int t = vox / S1C; int b = t % S1B; int a = t / S1B;
    int A[2], B[2], Cc[2]; int na=0, nb=0, nc=0;
    if (a & 1) { int q=(a-1)>>1; A[na++]=q; q=(a+1)>>1; if (q<S2A) A[na++]=q; } else A[na++]=a>>1;
    if (b & 1) { int q=(b-1)>>1; B[nb++]=q; q=(b+1)>>1; if (q<S2B) B[nb++]=q; } else B[nb++]=b>>1;
    if (c & 1) { int q=(c-1)>>1; Cc[nc++]=q; q=(c+1)>>1; if (q<S2C) Cc[nc++]=q; } else Cc[nc++]=c>>1;
    for (int ia = 0; ia < na; ia++)
        for (int ib = 0; ib < nb; ib++)
            for (int ic = 0; ic < nc; ic++)
                g_om2[(A[ia]*S2B + B[ib])*S2C + Cc[ic]] = 1;
}

// ---------------- gather sparse conv (SubM: STRIDE=1, down: STRIDE=2) ----------------
// out[row][co] = epilogue( sum_k sum_ci fin[lut[STRIDE*coord(row)+off_k-1]][ci] * W[k][ci][co] )
template<int CIN, int COUT, int STRIDE>
__global__ void __launch_bounds__(256) conv_kernel(
    const float* __restrict__ fin,
    const int* __restrict__ ovox,
    const int* __restrict__ nptr,
    const int* __restrict__ lut,
    int O1, int O2,                 // output-grid dims for decode (dim0 unused)
    int I0, int I1, int I2,         // input-grid dims
    const float* __restrict__ W,    // 27 x CIN x COUT
    float* fout,
    const float* __restrict__ bnp,  // [4][COUT] (gamma,beta,mean,var) or null
    const float* __restrict__ bias, // or null
    const float* resid,             // or null (may alias fout)
    int do_relu)
{
    constexpr int TM = 32;
    constexpr int CT = (COUT == 128) ? 4 : 2;
    constexpr int CG = COUT / CT;
    constexpr int RT = (TM*COUT)/(256*CT);
    constexpr int CK = (CIN < 32) ? CIN : 32;

    const int n = *nptr;
    const int base = blockIdx.x * TM;
    if (base >= n) return;

    __shared__ int s_idx[27][TM];
    __shared__ unsigned char s_tap[27];
    __shared__ float sA[TM][CIN+1];
    __shared__ float sW[CK][COUT];

    const int tid = threadIdx.x;
    if (tid < 27) s_tap[tid] = 0;
    __syncthreads();

    for (int e = tid; e < 27*TM; e += 256) {
        int k = e / TM, r = e % TM;
        int idx = -1;
        int row = base + r;
        if (row < n) {
            int vox = ovox[row];
            int c = vox % O2; int t = vox / O2; int b = t % O1; int a = t / O1;
            int n0 = STRIDE*a + (k/9) - 1;
            int n1 = STRIDE*b + ((k/3)%3) - 1;
            int n2 = STRIDE*c + (k%3) - 1;
            if (n0 >= 0 && n0 < I0 && n1 >= 0 && n1 < I1 && n2 >= 0 && n2 < I2)
                idx = lut[(n0*I1 + n1)*I2 + n2];
        }
        s_idx[k][r] = idx;
        if (idx >= 0) s_tap[k] = 1;
    }
    __syncthreads();

    const int cg = tid % CG;
    const int rg = tid / CG;

    float acc[RT][CT];
    #pragma unroll
    for (int r = 0; r < RT; r++)
        #pragma unroll
        for (int c = 0; c < CT; c++) acc[r][c] = 0.f;

    for (int k = 0; k < 27; k++) {
        if (!s_tap[k]) continue;              // uniform (shared) branch
        __syncthreads();                      // prior tap's reads of sA done
        for (int e = tid; e < TM*CIN; e += 256) {
            int r = e / CIN, ci = e % CIN;
            int id = s_idx[k][r];
            sA[r][ci] = (id >= 0) ? fin[(size_t)id*CIN + ci] : 0.f;
        }
        const float* Wk = W + (size_t)k*CIN*COUT;
        for (int ci0 = 0; ci0 < CIN; ci0 += CK) {
            __syncthreads();                  // sA ready / prior chunk's sW reads done
            for (int e = tid; e < CK*COUT; e += 256)
                sW[e / COUT][e % COUT] = Wk[(ci0 + e/COUT)*COUT + (e % COUT)];
            __syncthreads();
            #pragma unroll
            for (int ci = 0; ci < CK; ci++) {
                float a[RT], b[CT];
                #pragma unroll
                for (int r = 0; r < RT; r++) a[r] = sA[rg*RT + r][ci0 + ci];
                #pragma unroll
                for (int c = 0; c < CT; c++) b[c] = sW[ci][cg*CT + c];
                #pragma unroll
                for (int r = 0; r < RT; r++)
                    #pragma unroll
                    for (int c = 0; c < CT; c++) acc[r][c] += a[r]*b[c];
            }
        }
    }

    // epilogue: bn(eps=1e-3) or bias, + residual, relu
    float scl[CT], sh[CT];
    #pragma unroll
    for (int c = 0; c < CT; c++) {
        int co = cg*CT + c;
        if (bnp) {
            float g = bnp[co], be = bnp[COUT+co], mu = bnp[2*COUT+co], vv = bnp[3*COUT+co];
            float s = g * rsqrtf(vv + 1e-3f);
            scl[c] = s; sh[c] = be - mu*s;
        } else {
            scl[c] = 1.f; sh[c] = bias ? bias[co] : 0.f;
        }
    }
    #pragma unroll
    for (int r = 0; r < RT; r++) {
        int row = base + rg*RT + r;
        if (row >= n) continue;
        #pragma unroll
        for (int c = 0; c < CT; c++) {
            int co = cg*CT + c;
            float x = acc[r][c]*scl[c] + sh[c];
            if (resid) x += resid[(size_t)row*COUT + co];
            if (do_relu) x = fmaxf(x, 0.f);
            fout[(size_t)row*COUT + co] = x;
        }
    }
}

// ---------------- final GN(16) + relu + transposed dense scatter ----------------
__global__ void finalize_kernel(const float* __restrict__ gg, const float* __restrict__ gb,
                                float* __restrict__ out)
{
    int warp = (blockIdx.x*blockDim.x + threadIdx.x) >> 5;
    int lane = threadIdx.x & 31;
    if (warp >= g_cnt[1]) return;
    int row = warp;
    float4 fv = *reinterpret_cast<const float4*>(&g_f2b[(size_t)row*128 + lane*4]);
    float f[4] = {fv.x, fv.y, fv.z, fv.w};
    float s = f[0]+f[1]+f[2]+f[3];
    s += __shfl_xor_sync(0xffffffff, s, 1);
    float m = s * 0.125f;
    float q = 0.f;
    #pragma unroll
    for (int jj = 0; jj < 4; jj++) { float d = f[jj]-m; q += d*d; }
    q += __shfl_xor_sync(0xffffffff, q, 1);
    float rr = rsqrtf(q*0.125f + 1e-5f);
    int vox = g_oc2[row];
    int a2 = vox % S2C; int t = vox / S2C; int a1 = t % S2B; int a0 = t / S2B;
    #pragma unroll
    for (int jj = 0; jj < 4; jj++) {
        int c = lane*4 + jj;
        float y = (f[jj]-m)*rr*gg[c] + gb[c];
        y = fmaxf(y, 0.f);
        out[(((size_t)c*S2C + a2)*S2B + a1)*S2A + a0] = y;
    }
}

// ---------------- launch ----------------
extern "C" void kernel_launch(void* const* d_in, const int* in_sizes, int n_in,
                              void* d_out, int out_size)
{
    // batch_size may or may not appear as a size-1 input at index 2
    int has_bs = (n_in < 3 || in_sizes[2] == 1) ? 1 : 0;
    #define GI(i) ((const float*)d_in[((i) >= 2 && !has_bs) ? (i)-1 : (i)])

    const float* vf    = (const float*)d_in[0];
    const int*   coors = (const int*)d_in[1];
    const float* ele_t = GI(3);
    const float* azi_t = GI(4);
    const float* wq = GI(5),  *bq = GI(6);
    const float* wk = GI(7),  *bk = GI(8);
    const float* wv = GI(9),  *bv = GI(10);
    const float* w_in = GI(11), *b_in = GI(12), *gin_g = GI(13), *gin_b = GI(14);
    const float* w_d1 = GI(15), *bn_d1 = GI(16);
    const float* w_r1 = GI(17), *bn_r1 = GI(18);
    const float* w_d2 = GI(19), *bn_d2 = GI(20);
    const float* w_r2 = GI(21), *bn_r2 = GI(22);
    const float* w_out = GI(23), *b_out = GI(24), *gout_g = GI(25), *gout_b = GI(26);

    void* p;
    cudaGetSymbolAddress(&p, g_f0);   float* f0p  = (float*)p;
    cudaGetSymbolAddress(&p, g_f1a);  float* f1ap = (float*)p;
    cudaGetSymbolAddress(&p, g_f1b);  float* f1bp = (float*)p;
    cudaGetSymbolAddress(&p, g_f2a);  float* f2ap = (float*)p;
    cudaGetSymbolAddress(&p, g_f2b);  float* f2bp = (float*)p;
    cudaGetSymbolAddress(&p, g_lut0); int* lut0p = (int*)p;
    cudaGetSymbolAddress(&p, g_lut1); int* lut1p = (int*)p;
    cudaGetSymbolAddress(&p, g_lut2); int* lut2p = (int*)p;
    cudaGetSymbolAddress(&p, g_oc1);  int* oc1p  = (int*)p;
    cudaGetSymbolAddress(&p, g_oc2);  int* oc2p  = (int*)p;
    cudaGetSymbolAddress(&p, g_cnt);  int* cntp  = (int*)p;
    cudaGetSymbolAddress(&p, g_om1);  unsigned char* om1p = (unsigned char*)p;
    cudaGetSymbolAddress(&p, g_om2);  unsigned char* om2p = (unsigned char*)p;

    cudaMemsetAsync(lut0p, 0xFF, sizeof(int)*(size_t)L0VOX);
    cudaMemsetAsync(lut1p, 0xFF, sizeof(int)*(size_t)L1VOX);
    cudaMemsetAsync(lut2p, 0xFF, sizeof(int)*(size_t)L2VOX);
    cudaMemsetAsync(om1p, 0, (size_t)L1VOX);
    cudaMemsetAsync(om2p, 0, (size_t)L2VOX);
    cudaMemsetAsync(cntp, 0, 2*sizeof(int));
    cudaMemsetAsync(d_out, 0, (size_t)out_size*sizeof(float));

    attn_kernel<<<NROW, 256>>>(vf, coors, ele_t, azi_t, wq, bq, wk, bk, wv, bv);
    point_kernel<<<(NPTS+255)/256, 256>>>(coors, w_in, b_in, gin_g, gin_b);
    compact_kernel<<<(L1VOX+255)/256, 256>>>(om1p, lut1p, oc1p, cntp, L1VOX, CAP1);
    mark2_kernel<<<(CAP1+255)/256, 256>>>();
    compact_kernel<<<(L2VOX+255)/256, 256>>>(om2p, lut2p, oc2p, cntp+1, L2VOX, CAP2);

    const int GB1 = (CAP1+31)/32;
    const int GB2 = (CAP2+31)/32;
    const int WR1 = 27*32*32;    // 27648
    const int WR2 = 27*128*128;  // 442368

    // level-1: downsample 16->32 (bn+relu)
    conv_kernel<16,32,2><<<GB1,256>>>(f0p, oc1p, cntp, lut0p, S1B, S1C, S0A, S0B, S0C,
                                      w_d1, f1ap, bn_d1, nullptr, nullptr, 1);
    // level-1 basic blocks (2x: conv-bn-relu, conv-bn + residual, relu)
    conv_kernel<32,32,1><<<GB1,256>>>(f1ap, oc1p, cntp, lut1p, S1B, S1C, S1A, S1B, S1C,
                                      w_r1 + 0*WR1, f1bp, bn_r1 + 0*128, nullptr, nullptr, 1);
    conv_kernel<32,32,1><<<GB1,256>>>(f1bp, oc1p, cntp, lut1p, S1B, S1C, S1A, S1B, S1C,
                                      w_r1 + 1*WR1, f1ap, bn_r1 + 1*128, nullptr, f1ap, 1);
    conv_kernel<32,32,1><<<GB1,256>>>(f1ap, oc1p, cntp, lut1p, S1B, S1C, S1A, S1B, S1C,
                                      w_r1 + 2*WR1, f1bp, bn_r1 + 2*128, nullptr, nullptr, 1);
    conv_kernel<32,32,1><<<GB1,256>>>(f1bp, oc1p, cntp, lut1p, S1B, S1C, S1A, S1B, S1C,
                                      w_r1 + 3*WR1, f1ap, bn_r1 + 3*128, nullptr, f1ap, 1);
    // level-2: downsample 32->128 (bn+relu)
    conv_kernel<32,128,2><<<GB2,256>>>(f1ap, oc2p, cntp+1, lut1p, S2B, S2C, S1A, S1B, S1C,
                                       w_d2, f2ap, bn_d2, nullptr, nullptr, 1);
    // level-2 basic blocks
    conv_kernel<128,128,1><<<GB2,256>>>(f2ap, oc2p, cntp+1, lut2p, S2B, S2C, S2A, S2B, S2C,
                                        w_r2 + 0*WR2, f2bp, bn_r2 + 0*512, nullptr, nullptr, 1);
    conv_kernel<128,128,1><<<GB2,256>>>(f2bp, oc2p, cntp+1, lut2p, S2B, S2C, S2A, S2B, S2C,
                                        w_r2 + 1*WR2, f2ap, bn_r2 + 1*512, nullptr, f2ap, 1);
    conv_kernel<128,128,1><<<GB2,256>>>(f2ap, oc2p, cntp+1, lut2p, S2B, S2C, S2A, S2B, S2C,
                                        w_r2 + 2*WR2, f2bp, bn_r2 + 2*512, nullptr, nullptr, 1);
    conv_kernel<128,128,1><<<GB2,256>>>(f2bp, oc2p, cntp+1, lut2p, S2B, S2C, S2A, S2B, S2C,
                                        w_r2 + 3*WR2, f2ap, bn_r2 + 3*512, nullptr, f2ap, 1);
    // output conv 128->128 (+bias only)
    conv_kernel<128,128,1><<<GB2,256>>>(f2ap, oc2p, cntp+1, lut2p, S2B, S2C, S2A, S2B, S2C,
                                        w_out, f2bp, nullptr, b_out, nullptr, 0);
    // GN(16)+relu + transposed dense scatter
    finalize_kernel<<<(CAP2+7)/8, 256>>>(gout_g, gout_b, (float*)d_out);
}

// round 15
// speedup vs baseline: 1.8981x; 1.8981x over previous
#include <cuda_runtime.h>
#include <math.h>

// ---------------- problem constants ----------------
#define NPTS 43750
#define NROW 175
#define KTOK 250

#define S0A 56
#define S0B 350
#define S0C 512
#define S1A 28
#define S1B 175
#define S1C 256
#define S2A 14
#define S2B 88
#define S2C 128

#define CAP1 350000
#define CAP2 69000

#define L0VOX (S0A*S0B*S0C)   // 10,035,200
#define L1VOX (S1A*S1B*S1C)   // 1,254,400
#define L2VOX (S2A*S2B*S2C)   // 157,696

// ---------------- scratch (static device globals; no allocation) ----------------
__device__ float g_fatt[NPTS];
__device__ float g_f0[NPTS*16];
__device__ int g_lut0[L0VOX];
__device__ unsigned char g_om1[L1VOX];
__device__ int g_lut1[L1VOX];
__device__ int g_oc1[CAP1];
__device__ unsigned char g_om2[L2VOX];
__device__ int g_lut2[L2VOX];
__device__ int g_oc2[CAP2];
__device__ int g_cnt[2];
__device__ float g_f1a[CAP1*32];
__device__ float g_f1b[CAP1*32];
__device__ float g_f2a[CAP2*128];
__device__ float g_f2b[CAP2*128];

// ---------------- attention (per radar row, 4 layers) ----------------
__global__ void __launch_bounds__(256) attn_kernel(
    const float* __restrict__ vf, const int* __restrict__ coors,
    const float* __restrict__ ele_t, const float* __restrict__ azi_t,
    const float* __restrict__ wq, const float* __restrict__ bq,
    const float* __restrict__ wk, const float* __restrict__ bk,
    const float* __restrict__ wv, const float* __restrict__ bv)
{
    __shared__ float sx[KTOK];
    __shared__ float sea[KTOK][6];
    __shared__ float sk[KTOK][32];
    __shared__ float sv[KTOK];

    const int r = blockIdx.x;
    const int tid = threadIdx.x;
    const int j = tid;

    if (j < KTOK) {
        int i = r*KTOK + j;
        sx[j] = log10f(vf[2*i]);           // voxel_features[:, -2] == col 0
        int c1 = coors[4*i+1], c3 = coors[4*i+3];
        sea[j][0]=ele_t[c1*3+0]; sea[j][1]=ele_t[c1*3+1]; sea[j][2]=ele_t[c1*3+2];
        sea[j][3]=azi_t[c3*3+0]; sea[j][4]=azi_t[c3*3+1]; sea[j][5]=azi_t[c3*3+2];
    }
    __syncthreads();

    const float scale = 0.17677669529663687f;  // 32^-0.5

    for (int l = 0; l < 4; l++) {
        for (int t = tid; t < KTOK*32; t += 256) {
            int jj = t >> 5, d = t & 31;
            const float* w = wk + l*7*32 + d;
            float acc = bk[l*32+d] + sx[jj]*w[0];
            #pragma unroll
            for (int u = 0; u < 6; u++) acc += sea[jj][u]*w[(u+1)*32];
            sk[jj][d] = acc;
        }
        for (int t = tid; t < KTOK; t += 256) {
            const float* w = wv + l*7;
            float acc = bv[l] + sx[t]*w[0];
            #pragma unroll
            for (int u = 0; u < 6; u++) acc += sea[t][u]*w[u+1];
            sv[t] = acc;
        }
        __syncthreads();

        float xn = 0.f;
        if (j < KTOK) {
            float q[32];
            #pragma unroll
            for (int d = 0; d < 32; d++) {
                const float* w = wq + l*7*32 + d;
                float acc = bq[l*32+d] + sx[j]*w[0];
                #pragma unroll
                for (int u = 0; u < 6; u++) acc += sea[j][u]*w[(u+1)*32];
                q[d] = acc;
            }
            float m = -1e30f, s = 0.f, a = 0.f;
            for (int jj = 0; jj < KTOK; jj++) {
                float dot = 0.f;
                #pragma unroll
                for (int d = 0; d < 32; d++) dot += q[d]*sk[jj][d];
                dot *= scale;
                float nm = fmaxf(m, dot);
                float corr = expf(m - nm);
                float p = expf(dot - nm);
                s = s*corr + p;
                a = a*corr + p*sv[jj];
                m = nm;
            }
            xn = a / s;
        }
        __syncthreads();
        if (j < KTOK) sx[j] = xn;
        __syncthreads();
    }
    if (j < KTOK) g_fatt[r*KTOK + j] = sx[j];
}

// ---------------- per-point: stem MLP + GN(8) + relu, build lut0, mark om1 ----------------
__global__ void point_kernel(const int* __restrict__ coors,
                             const float* __restrict__ w_in, const float* __restrict__ b_in,
                             const float* __restrict__ gg, const float* __restrict__ gb)
{
    int i = blockIdx.x*blockDim.x + threadIdx.x;
    if (i >= NPTS) return;
    int c1 = coors[4*i+1], c2 = coors[4*i+2], c3 = coors[4*i+3];
    int ele = 2*c1-9, rng = 2*c2, azi = 2*c3+149;
    float f[4] = {(float)ele, (float)rng, (float)azi, g_fatt[i]};
    float y[16];
    #pragma unroll
    for (int c = 0; c < 16; c++) {
        float acc = b_in[c];
        #pragma unroll
        for (int t = 0; t < 4; t++) acc += f[t]*w_in[t*16+c];
        y[c] = acc;
    }
    #pragma unroll
    for (int g = 0; g < 8; g++) {
        float a = y[2*g], b = y[2*g+1];
        float m = 0.5f*(a+b);
        float va = 0.5f*((a-m)*(a-m)+(b-m)*(b-m));
        float rr = rsqrtf(va + 1e-5f);
        float o0 = (a-m)*rr*gg[2*g]   + gb[2*g];
        float o1 = (b-m)*rr*gg[2*g+1] + gb[2*g+1];
        g_f0[i*16+2*g]   = fmaxf(o0, 0.f);
        g_f0[i*16+2*g+1] = fmaxf(o1, 0.f);
    }
    int vox = (ele*S0B + rng)*S0C + azi;
    atomicMax(&g_lut0[vox], i);           // last-wins for duplicate coords
    int o0a = (ele-1)>>1;
    int o1  = rng>>1;
    int o2a = (azi-1)>>1;
    #pragma unroll
    for (int d0 = 0; d0 < 2; d0++) {
        int o0 = o0a + d0; if (o0 < 0 || o0 >= S1A) continue;
        #pragma unroll
        for (int d2 = 0; d2 < 2; d2++) {
            int o2 = o2a + d2; if (o2 < 0 || o2 >= S1C) continue;
            g_om1[(o0*S1B + o1)*S1C + o2] = 1;
        }
    }
}

// ---------------- compact active voxels -> (oc list, lut, count) ----------------
__global__ void compact_kernel(const unsigned char* __restrict__ om, int* lut, int* oc,
                               int* cnt, int nvox, int cap)
{
    int v = blockIdx.x*blockDim.x + threadIdx.x;
    bool act = (v < nvox) && om[v];
    __shared__ int s_base, s_cnt;
    if (threadIdx.x == 0) s_cnt = 0;
    __syncthreads();
    int r = 0;
    if (act) r = atomicAdd(&s_cnt, 1);
    __syncthreads();
    if (threadIdx.x == 0) s_base = s_cnt ? atomicAdd(cnt, s_cnt) : 0;
    __syncthreads();
    if (act) {
        int pos = s_base + r;
        if (pos < cap) { oc[pos] = v; lut[v] = pos; }
    }
}

// ---------------- mark level-2 downsample mask from oc1 ----------------
__global__ void mark2_kernel()
{
    int i = blockIdx.x*blockDim.x + threadIdx.x;
    if (i >= g_cnt[0]) return;
    int vox = g_oc1[i];
    int c = vox % S1C; int t = vox / S1C; int b = t % S1B; int a = t / S1B;
    int A[2], B[2], Cc[2]; int na=0, nb=0, nc=0;
    if (a & 1) { int q=(a-1)>>1; A[na++]=q; q=(a+1)>>1; if (q<S2A) A[na++]=q; } else A[na++]=a>>1;
    if (b & 1) { int q=(b-1)>>1; B[nb++]=q; q=(b+1)>>1; if (q<S2B) B[nb++]=q; } else B[nb++]=b>>1;
    if (c & 1) { int q=(c-1)>>1; Cc[nc++]=q; q=(c+1)>>1; if (q<S2C) Cc[nc++]=q; } else Cc[nc++]=c>>1;
    for (int ia = 0; ia < na; ia++)
        for (int ib = 0; ib < nb; ib++)
            for (int ic = 0; ic < nc; ic++)
                g_om2[(A[ia]*S2B + B[ib])*S2C + Cc[ic]] = 1;
}

// ---------------- gather sparse conv, packed f32x2 micro-kernel ----------------
// Per-thread tile: 4 rows x 8 channels (4 channel-pairs) accumulated in f32x2.
// A staged in smem as duplicated float2 (a,a) with +2 pad; B channel pairs
// remapped co = 2*cg + (COUT/4)*cp so per-warp weight LDS.64 hits one 128B row.
template<int CIN, int COUT, int STRIDE, int TM>
__global__ void __launch_bounds__((TM/4)*(COUT/8)) convx_kernel(
    const float* __restrict__ fin,
    const int* __restrict__ ovox,
    const int* __restrict__ nptr,
    const int* __restrict__ lut,
    int O1, int O2,                 // output-grid dims for decode
    int I0, int I1, int I2,         // input-grid dims
    const float* __restrict__ W,    // 27 x CIN x COUT
    float* __restrict__ fout,
    const float* __restrict__ bnp,  // [4][COUT] or null
    const float* __restrict__ bias, // or null
    const float* __restrict__ resid,// or null (may alias fout)
    int do_relu)
{
    constexpr int CGn = COUT/8;
    constexpr int THREADS = (TM/4)*CGn;
    constexpr int CK  = (CIN < 32) ? CIN : 32;
    constexpr int NCH = CIN / CK;
    constexpr int AROW = CIN + 2;   // float2 units, keeps 16B alignment + de-conflicts rows
    constexpr int RSTEP = TM/4;     // strided row mapping

    extern __shared__ char smem[];
    int* s_idx = (int*)smem;                                   // 27*TM
    unsigned char* s_tap = (unsigned char*)(smem + 27*TM*4);   // 32
    float2* sAd = (float2*)(smem + 27*TM*4 + 32);              // TM*AROW
    float*  sW  = (float*)(smem + 27*TM*4 + 32 + (size_t)TM*AROW*8); // CK*COUT

    const int n = *nptr;
    const int base = blockIdx.x * TM;
    if (base >= n) return;

    const int tid = threadIdx.x;
    if (tid < 27) s_tap[tid] = 0;
    __syncthreads();

    for (int e = tid; e < 27*TM; e += THREADS) {
        int k = e / TM, r = e - k*TM;
        int idx = -1;
        int row = base + r;
        if (row < n) {
            int vox = ovox[row];
            int c = vox % O2; int t = vox / O2; int b = t % O1; int a = t / O1;
            int n0 = STRIDE*a + (k/9) - 1;
            int n1 = STRIDE*b + ((k/3)%3) - 1;
            int n2 = STRIDE*c + (k%3) - 1;
            if (n0 >= 0 && n0 < I0 && n1 >= 0 && n1 < I1 && n2 >= 0 && n2 < I2)
                idx = lut[(n0*I1 + n1)*I2 + n2];
        }
        s_idx[k*TM + r] = idx;
        if (idx >= 0) s_tap[k] = 1;
    }
    __syncthreads();

    const int rg = tid / CGn;
    const int cg = tid - rg*CGn;

    unsigned long long acc[4][4];
    #pragma unroll
    for (int r = 0; r < 4; r++)
        #pragma unroll
        for (int cp = 0; cp < 4; cp++) acc[r][cp] = 0ULL;

    for (int k = 0; k < 27; k++) {
        if (!s_tap[k]) continue;              // uniform branch
        __syncthreads();                      // prior tap's sAd reads done
        for (int e = tid; e < TM*CIN; e += THREADS) {
            int r = e / CIN, ci = e - r*CIN;
            int id = s_idx[k*TM + r];
            float v = (id >= 0) ? fin[(size_t)id*CIN + ci] : 0.f;
            sAd[r*AROW + ci] = make_float2(v, v);
        }
        const float* Wk = W + (size_t)k*CIN*COUT;
        for (int ch = 0; ch < NCH; ch++) {
            __syncthreads();                  // prior sW reads done (and sAd ready for ch 0 via next sync)
            const float* Wc = Wk + (size_t)ch*CK*COUT;
            for (int e = tid; e < CK*COUT; e += THREADS)
                sW[e] = Wc[e];
            __syncthreads();                  // sW (and sAd) ready
            const float2* aBase = sAd + ch*CK;
            #pragma unroll
            for (int s = 0; s < CK; s += 2) {
                ulonglong2 a2[4];
                #pragma unroll
                for (int r = 0; r < 4; r++)
                    a2[r] = *reinterpret_cast<const ulonglong2*>(aBase + (rg + r*RSTEP)*AROW + s);
                unsigned long long b0[4], b1[4];
                #pragma unroll
                for (int cp = 0; cp < 4; cp++) {
                    int co = 2*cg + (COUT/4)*cp;
                    b0[cp] = *reinterpret_cast<const unsigned long long*>(sW + s*COUT + co);
                    b1[cp] = *reinterpret_cast<const unsigned long long*>(sW + (s+1)*COUT + co);
                }
                #pragma unroll
                for (int r = 0; r < 4; r++) {
                    #pragma unroll
                    for (int cp = 0; cp < 4; cp++)
                        asm("fma.rn.f32x2 %0, %1, %2, %0;" : "+l"(acc[r][cp]) : "l"(a2[r].x), "l"(b0[cp]));
                    #pragma unroll
                    for (int cp = 0; cp < 4; cp++)
                        asm("fma.rn.f32x2 %0, %1, %2, %0;" : "+l"(acc[r][cp]) : "l"(a2[r].y), "l"(b1[cp]));
                }
            }
        }
    }

    // epilogue: bn(eps=1e-3) or bias, + residual, relu
    #pragma unroll
    for (int cp = 0; cp < 4; cp++) {
        int co = 2*cg + (COUT/4)*cp;
        float scl0, sh0, scl1, sh1;
        if (bnp) {
            float g0 = bnp[co],   be0 = bnp[COUT+co],   mu0 = bnp[2*COUT+co],   vv0 = bnp[3*COUT+co];
            float g1 = bnp[co+1], be1 = bnp[COUT+co+1], mu1 = bnp[2*COUT+co+1], vv1 = bnp[3*COUT+co+1];
            scl0 = g0 * rsqrtf(vv0 + 1e-3f); sh0 = be0 - mu0*scl0;
            scl1 = g1 * rsqrtf(vv1 + 1e-3f); sh1 = be1 - mu1*scl1;
        } else {
            scl0 = 1.f; scl1 = 1.f;
            sh0 = bias ? bias[co]   : 0.f;
            sh1 = bias ? bias[co+1] : 0.f;
        }
        #pragma unroll
        for (int r = 0; r < 4; r++) {
            int row = base + rg + r*RSTEP;
            if (row >= n) continue;
            union { unsigned long long u; float2 f; } cv; cv.u = acc[r][cp];
            float2 v = cv.f;
            v.x = v.x*scl0 + sh0;
            v.y = v.y*scl1 + sh1;
            if (resid) {
                float2 rv = *reinterpret_cast<const float2*>(resid + (size_t)row*COUT + co);
                v.x += rv.x; v.y += rv.y;
            }
            if (do_relu) { v.x = fmaxf(v.x, 0.f); v.y = fmaxf(v.y, 0.f); }
            *reinterpret_cast<float2*>(fout + (size_t)row*COUT + co) = v;
        }
    }
}

// ---------------- final GN(16) + relu + transposed dense scatter ----------------
__global__ void finalize_kernel(const float* __restrict__ gg, const float* __restrict__ gb,
                                float* __restrict__ out)
{
    int warp = (blockIdx.x*blockDim.x + threadIdx.x) >> 5;
    int lane = threadIdx.x & 31;
    if (warp >= g_cnt[1]) return;
    int row = warp;
    float4 fv = *reinterpret_cast<const float4*>(&g_f2b[(size_t)row*128 + lane*4]);
    float f[4] = {fv.x, fv.y, fv.z, fv.w};
    float s = f[0]+f[1]+f[2]+f[3];
    s += __shfl_xor_sync(0xffffffff, s, 1);
    float m = s * 0.125f;
    float q = 0.f;
    #pragma unroll
    for (int jj = 0; jj < 4; jj++) { float d = f[jj]-m; q += d*d; }
    q += __shfl_xor_sync(0xffffffff, q, 1);
    float rr = rsqrtf(q*0.125f + 1e-5f);
    int vox = g_oc2[row];
    int a2 = vox % S2C; int t = vox / S2C; int a1 = t % S2B; int a0 = t / S2B;
    #pragma unroll
    for (int jj = 0; jj < 4; jj++) {
        int c = lane*4 + jj;
        float y = (f[jj]-m)*rr*gg[c] + gb[c];
        y = fmaxf(y, 0.f);
        out[(((size_t)c*S2C + a2)*S2B + a1)*S2A + a0] = y;
    }
}

// smem bytes for a convx instantiation
static inline size_t convx_smem(int TM, int CIN, int COUT) {
    int CK = (CIN < 32) ? CIN : 32;
    return (size_t)27*TM*4 + 32 + (size_t)TM*(CIN+2)*8 + (size_t)CK*COUT*4;
}

// ---------------- launch ----------------
extern "C" void kernel_launch(void* const* d_in, const int* in_sizes, int n_in,
                              void* d_out, int out_size)
{
    int has_bs = (n_in < 3 || in_sizes[2] == 1) ? 1 : 0;
    #define GI(i) ((const float*)d_in[((i) >= 2 && !has_bs) ? (i)-1 : (i)])

    const float* vf    = (const float*)d_in[0];
    const int*   coors = (const int*)d_in[1];
    const float* ele_t = GI(3);
    const float* azi_t = GI(4);
    const float* wq = GI(5),  *bq = GI(6);
    const float* wk = GI(7),  *bk = GI(8);
    const float* wv = GI(9),  *bv = GI(10);
    const float* w_in = GI(11), *b_in = GI(12), *gin_g = GI(13), *gin_b = GI(14);
    const float* w_d1 = GI(15), *bn_d1 = GI(16);
    const float* w_r1 = GI(17), *bn_r1 = GI(18);
    const float* w_d2 = GI(19), *bn_d2 = GI(20);
    const float* w_r2 = GI(21), *bn_r2 = GI(22);
    const float* w_out = GI(23), *b_out = GI(24), *gout_g = GI(25), *gout_b = GI(26);

    void* p;
    cudaGetSymbolAddress(&p, g_f0);   float* f0p  = (float*)p;
    cudaGetSymbolAddress(&p, g_f1a);  float* f1ap = (float*)p;
    cudaGetSymbolAddress(&p, g_f1b);  float* f1bp = (float*)p;
    cudaGetSymbolAddress(&p, g_f2a);  float* f2ap = (float*)p;
    cudaGetSymbolAddress(&p, g_f2b);  float* f2bp = (float*)p;
    cudaGetSymbolAddress(&p, g_lut0); int* lut0p = (int*)p;
    cudaGetSymbolAddress(&p, g_lut1); int* lut1p = (int*)p;
    cudaGetSymbolAddress(&p, g_lut2); int* lut2p = (int*)p;
    cudaGetSymbolAddress(&p, g_oc1);  int* oc1p  = (int*)p;
    cudaGetSymbolAddress(&p, g_oc2);  int* oc2p  = (int*)p;
    cudaGetSymbolAddress(&p, g_cnt);  int* cntp  = (int*)p;
    cudaGetSymbolAddress(&p, g_om1);  unsigned char* om1p = (unsigned char*)p;
    cudaGetSymbolAddress(&p, g_om2);  unsigned char* om2p = (unsigned char*)p;

    // enable >48KB dynamic smem for the conv instantiations (idempotent)
    size_t sm_d1  = convx_smem(128, 16, 32);
    size_t sm_r1  = convx_smem(128, 32, 32);
    size_t sm_d2  = convx_smem(64, 32, 128);
    size_t sm_r2  = convx_smem(64, 128, 128);
    cudaFuncSetAttribute((const void*)convx_kernel<16,32,2,128>,   cudaFuncAttributeMaxDynamicSharedMemorySize, (int)sm_d1);
    cudaFuncSetAttribute((const void*)convx_kernel<32,32,1,128>,   cudaFuncAttributeMaxDynamicSharedMemorySize, (int)sm_r1);
    cudaFuncSetAttribute((const void*)convx_kernel<32,128,2,64>,   cudaFuncAttributeMaxDynamicSharedMemorySize, (int)sm_d2);
    cudaFuncSetAttribute((const void*)convx_kernel<128,128,1,64>,  cudaFuncAttributeMaxDynamicSharedMemorySize, (int)sm_r2);

    cudaMemsetAsync(lut0p, 0xFF, sizeof(int)*(size_t)L0VOX);
    cudaMemsetAsync(lut1p, 0xFF, sizeof(int)*(size_t)L1VOX);
    cudaMemsetAsync(lut2p, 0xFF, sizeof(int)*(size_t)L2VOX);
    cudaMemsetAsync(om1p, 0, (size_t)L1VOX);
    cudaMemsetAsync(om2p, 0, (size_t)L2VOX);
    cudaMemsetAsync(cntp, 0, 2*sizeof(int));
    cudaMemsetAsync(d_out, 0, (size_t)out_size*sizeof(float));

    attn_kernel<<<NROW, 256>>>(vf, coors, ele_t, azi_t, wq, bq, wk, bk, wv, bv);
    point_kernel<<<(NPTS+255)/256, 256>>>(coors, w_in, b_in, gin_g, gin_b);
    compact_kernel<<<(L1VOX+255)/256, 256>>>(om1p, lut1p, oc1p, cntp, L1VOX, CAP1);
    mark2_kernel<<<(CAP1+255)/256, 256>>>();
    compact_kernel<<<(L2VOX+255)/256, 256>>>(om2p, lut2p, oc2p, cntp+1, L2VOX, CAP2);

    const int G1 = (CAP1+127)/128;   // TM=128 configs
    const int G2 = (CAP2+63)/64;     // TM=64 configs
    const int T32 = (128/4)*(32/8);  // 128 threads
    const int T128 = (64/4)*(128/8); // 256 threads
    const int WR1 = 27*32*32;    // 27648
    const int WR2 = 27*128*128;  // 442368

    // level-1: downsample 16->32 (bn+relu)
    convx_kernel<16,32,2,128><<<G1,T32,sm_d1>>>(f0p, oc1p, cntp, lut0p, S1B, S1C, S0A, S0B, S0C,
                                                w_d1, f1ap, bn_d1, nullptr, nullptr, 1);
    // level-1 basic blocks
    convx_kernel<32,32,1,128><<<G1,T32,sm_r1>>>(f1ap, oc1p, cntp, lut1p, S1B, S1C, S1A, S1B, S1C,
                                                w_r1 + 0*WR1, f1bp, bn_r1 + 0*128, nullptr, nullptr, 1);
    convx_kernel<32,32,1,128><<<G1,T32,sm_r1>>>(f1bp, oc1p, cntp, lut1p, S1B, S1C, S1A, S1B, S1C,
                                                w_r1 + 1*WR1, f1ap, bn_r1 + 1*128, nullptr, f1ap, 1);
    convx_kernel<32,32,1,128><<<G1,T32,sm_r1>>>(f1ap, oc1p, cntp, lut1p, S1B, S1C, S1A, S1B, S1C,
                                                w_r1 + 2*WR1, f1bp, bn_r1 + 2*128, nullptr, nullptr, 1);
    convx_kernel<32,32,1,128><<<G1,T32,sm_r1>>>(f1bp, oc1p, cntp, lut1p, S1B, S1C, S1A, S1B, S1C,
                                                w_r1 + 3*WR1, f1ap, bn_r1 + 3*128, nullptr, f1ap, 1);
    // level-2: downsample 32->128 (bn+relu)
    convx_kernel<32,128,2,64><<<G2,T128,sm_d2>>>(f1ap, oc2p, cntp+1, lut1p, S2B, S2C, S1A, S1B, S1C,
                                                 w_d2, f2ap, bn_d2, nullptr, nullptr, 1);
    // level-2 basic blocks
    convx_kernel<128,128,1,64><<<G2,T128,sm_r2>>>(f2ap, oc2p, cntp+1, lut2p, S2B, S2C, S2A, S2B, S2C,
                                                  w_r2 + 0*WR2, f2bp, bn_r2 + 0*512, nullptr, nullptr, 1);
    convx_kernel<128,128,1,64><<<G2,T128,sm_r2>>>(f2bp, oc2p, cntp+1, lut2p, S2B, S2C, S2A, S2B, S2C,
                                                  w_r2 + 1*WR2, f2ap, bn_r2 + 1*512, nullptr, f2ap, 1);
    convx_kernel<128,128,1,64><<<G2,T128,sm_r2>>>(f2ap, oc2p, cntp+1, lut2p, S2B, S2C, S2A, S2B, S2C,
                                                  w_r2 + 2*WR2, f2bp, bn_r2 + 2*512, nullptr, nullptr, 1);
    convx_kernel<128,128,1,64><<<G2,T128,sm_r2>>>(f2bp, oc2p, cntp+1, lut2p, S2B, S2C, S2A, S2B, S2C,
                                                  w_r2 + 3*WR2, f2ap, bn_r2 + 3*512, nullptr, f2ap, 1);
    // output conv 128->128 (+bias only)
    convx_kernel<128,128,1,64><<<G2,T128,sm_r2>>>(f2ap, oc2p, cntp+1, lut2p, S2B, S2C, S2A, S2B, S2C,
                                                  w_out, f2bp, nullptr, b_out, nullptr, 0);
    // GN(16)+relu + transposed dense scatter
    finalize_kernel<<<(CAP2+7)/8, 256>>>(gout_g, gout_b, (float*)d_out);
}

// round 17
// speedup vs baseline: 7.4180x; 3.9082x over previous
#include <cuda_runtime.h>
#include <math.h>
#include <stdint.h>

// tcgen05 only exists in the sm_103a ("arch-accelerated") device pass.
// The harness also emits a generic compute_103 PTX pass; give it a scalar
// fallback body so ptxas accepts it (it is never executed — cubin wins).
#if !defined(__CUDA_ARCH__) || defined(__CUDA_ARCH_FEAT_SM103_ALL)
#define TC_PATH 1
#else
#define TC_PATH 0
#endif

// ---------------- problem constants ----------------
#define NPTS 43750
#define NROW 175
#define KTOK 250

#define S0A 56
#define S0B 350
#define S0C 512
#define S1A 28
#define S1B 175
#define S1C 256
#define S2A 14
#define S2B 88
#define S2C 128

#define CAP1 350000
#define CAP2 69000

#define L0VOX (S0A*S0B*S0C)
#define L1VOX (S1A*S1B*S1C)
#define L2VOX (S2A*S2B*S2C)

#define WSLOT (27*16384)   // floats per prepped-weight slot (max CIN=128)

// ---------------- scratch (static device globals; no allocation) ----------------
__device__ float g_fatt[NPTS];
__device__ float g_f0[NPTS*16];
__device__ int g_lut0[L0VOX];
__device__ unsigned char g_om1[L1VOX];
__device__ int g_lut1[L1VOX];
__device__ int g_oc1[CAP1];
__device__ unsigned char g_om2[L2VOX];
__device__ int g_lut2[L2VOX];
__device__ int g_oc2[CAP2];
__device__ int g_cnt[2];
__device__ float g_f1a[CAP1*32];
__device__ float g_f1b[CAP1*32];
__device__ float g_f2a[CAP2*128];
__device__ float g_f2b[CAP2*128];
__device__ float g_wT[6*WSLOT];   // pre-swizzled B images: [d2, r2x4, out]

// ---------------- attention (per radar row, 4 layers) ----------------
__global__ void __launch_bounds__(256) attn_kernel(
    const float* __restrict__ vf, const int* __restrict__ coors,
    const float* __restrict__ ele_t, const float* __restrict__ azi_t,
    const float* __restrict__ wq, const float* __restrict__ bq,
    const float* __restrict__ wk, const float* __restrict__ bk,
    const float* __restrict__ wv, const float* __restrict__ bv)
{
    __shared__ float sx[KTOK];
    __shared__ float sea[KTOK][6];
    __shared__ float sk[KTOK][32];
    __shared__ float sv[KTOK];

    const int r = blockIdx.x;
    const int tid = threadIdx.x;
    const int j = tid;

    if (j < KTOK) {
        int i = r*KTOK + j;
        sx[j] = log10f(vf[2*i]);
        int c1 = coors[4*i+1], c3 = coors[4*i+3];
        sea[j][0]=ele_t[c1*3+0]; sea[j][1]=ele_t[c1*3+1]; sea[j][2]=ele_t[c1*3+2];
        sea[j][3]=azi_t[c3*3+0]; sea[j][4]=azi_t[c3*3+1]; sea[j][5]=azi_t[c3*3+2];
    }
    __syncthreads();

    const float scale = 0.17677669529663687f;

    for (int l = 0; l < 4; l++) {
        for (int t = tid; t < KTOK*32; t += 256) {
            int jj = t >> 5, d = t & 31;
            const float* w = wk + l*7*32 + d;
            float acc = bk[l*32+d] + sx[jj]*w[0];
            #pragma unroll
            for (int u = 0; u < 6; u++) acc += sea[jj][u]*w[(u+1)*32];
            sk[jj][d] = acc;
        }
        for (int t = tid; t < KTOK; t += 256) {
            const float* w = wv + l*7;
            float acc = bv[l] + sx[t]*w[0];
            #pragma unroll
            for (int u = 0; u < 6; u++) acc += sea[t][u]*w[u+1];
            sv[t] = acc;
        }
        __syncthreads();

        float xn = 0.f;
        if (j < KTOK) {
            float q[32];
            #pragma unroll
            for (int d = 0; d < 32; d++) {
                const float* w = wq + l*7*32 + d;
                float acc = bq[l*32+d] + sx[j]*w[0];
                #pragma unroll
                for (int u = 0; u < 6; u++) acc += sea[j][u]*w[(u+1)*32];
                q[d] = acc;
            }
            float m = -1e30f, s = 0.f, a = 0.f;
            for (int jj = 0; jj < KTOK; jj++) {
                float dot = 0.f;
                #pragma unroll
                for (int d = 0; d < 32; d++) dot += q[d]*sk[jj][d];
                dot *= scale;
                float nm = fmaxf(m, dot);
                float corr = expf(m - nm);
                float p = expf(dot - nm);
                s = s*corr + p;
                a = a*corr + p*sv[jj];
                m = nm;
            }
            xn = a / s;
        }
        __syncthreads();
        if (j < KTOK) sx[j] = xn;
        __syncthreads();
    }
    if (j < KTOK) g_fatt[r*KTOK + j] = sx[j];
}

// ---------------- per-point: stem MLP + GN(8) + relu, build lut0, mark om1 ----------------
__global__ void point_kernel(const int* __restrict__ coors,
                             const float* __restrict__ w_in, const float* __restrict__ b_in,
                             const float* __restrict__ gg, const float* __restrict__ gb)
{
    int i = blockIdx.x*blockDim.x + threadIdx.x;
    if (i >= NPTS) return;
    int c1 = coors[4*i+1], c2 = coors[4*i+2], c3 = coors[4*i+3];
    int ele = 2*c1-9, rng = 2*c2, azi = 2*c3+149;
    float f[4] = {(float)ele, (float)rng, (float)azi, g_fatt[i]};
    float y[16];
    #pragma unroll
    for (int c = 0; c < 16; c++) {
        float acc = b_in[c];
        #pragma unroll
        for (int t = 0; t < 4; t++) acc += f[t]*w_in[t*16+c];
        y[c] = acc;
    }
    #pragma unroll
    for (int g = 0; g < 8; g++) {
        float a = y[2*g], b = y[2*g+1];
        float m = 0.5f*(a+b);
        float va = 0.5f*((a-m)*(a-m)+(b-m)*(b-m));
        float rr = rsqrtf(va + 1e-5f);
        float o0 = (a-m)*rr*gg[2*g]   + gb[2*g];
        float o1 = (b-m)*rr*gg[2*g+1] + gb[2*g+1];
        g_f0[i*16+2*g]   = fmaxf(o0, 0.f);
        g_f0[i*16+2*g+1] = fmaxf(o1, 0.f);
    }
    int vox = (ele*S0B + rng)*S0C + azi;
    atomicMax(&g_lut0[vox], i);
    int o0a = (ele-1)>>1;
    int o1  = rng>>1;
    int o2a = (azi-1)>>1;
    #pragma unroll
    for (int d0 = 0; d0 < 2; d0++) {
        int o0 = o0a + d0; if (o0 < 0 || o0 >= S1A) continue;
        #pragma unroll
        for (int d2 = 0; d2 < 2; d2++) {
            int o2 = o2a + d2; if (o2 < 0 || o2 >= S1C) continue;
            g_om1[(o0*S1B + o1)*S1C + o2] = 1;
        }
    }
}

// ---------------- compact active voxels ----------------
__global__ void compact_kernel(const unsigned char* __restrict__ om, int* lut, int* oc,
                               int* cnt, int nvox, int cap)
{
    int v = blockIdx.x*blockDim.x + threadIdx.x;
    bool act = (v < nvox) && om[v];
    __shared__ int s_base, s_cnt;
    if (threadIdx.x == 0) s_cnt = 0;
    __syncthreads();
    int r = 0;
    if (act) r = atomicAdd(&s_cnt, 1);
    __syncthreads();
    if (threadIdx.x == 0) s_base = s_cnt ? atomicAdd(cnt, s_cnt) : 0;
    __syncthreads();
    if (act) {
        int pos = s_base + r;
        if (pos < cap) { oc[pos] = v; lut[v] = pos; }
    }
}

// ---------------- mark level-2 downsample mask ----------------
__global__ void mark2_kernel()
{
    int i = blockIdx.x*blockDim.x + threadIdx.x;
    if (i >= g_cnt[0]) return;
    int vox = g_oc1[i];
    int c = vox % S1C; int t = vox / S1C; int b = t % S1B; int a = t / S1B;
    int A[2], B[2], Cc[2]; int na=0, nb=0, nc=0;
    if (a & 1) { int q=(a-1)>>1; A[na++]=q; q=(a+1)>>1; if (q<S2A) A[na++]=q; } else A[na++]=a>>1;
    if (b & 1) { int q=(b-1)>>1; B[nb++]=q; q=(b+1)>>1; if (q<S2B) B[nb++]=q; } else B[nb++]=b>>1;
    if (c & 1) { int q=(c-1)>>1; Cc[nc++]=q; q=(c+1)>>1; if (q<S2C) Cc[nc++]=q; } else Cc[nc++]=c>>1;
    for (int ia = 0; ia < na; ia++)
        for (int ib = 0; ib < nb; ib++)
            for (int ic = 0; ic < nc; ic++)
                g_om2[(A[ia]*S2B + B[ib])*S2C + Cc[ic]] = 1;
}

// ---------------- scalar f32x2 conv (kept for level-1) ----------------
template<int CIN, int COUT, int STRIDE, int TM>
__global__ void __launch_bounds__((TM/4)*(COUT/8)) convx_kernel(
    const float* __restrict__ fin,
    const int* __restrict__ ovox,
    const int* __restrict__ nptr,
    const int* __restrict__ lut,
    int O1, int O2, int I0, int I1, int I2,
    const float* __restrict__ W,
    float* __restrict__ fout,
    const float* __restrict__ bnp,
    const float* __restrict__ bias,
    const float* __restrict__ resid,
    int do_relu)
{
    constexpr int CGn = COUT/8;
    constexpr int THREADS = (TM/4)*CGn;
    constexpr int CK  = (CIN < 32) ? CIN : 32;
    constexpr int NCH = CIN / CK;
    constexpr int AROW = CIN + 2;
    constexpr int RSTEP = TM/4;

    extern __shared__ char smem[];
    int* s_idx = (int*)smem;
    unsigned char* s_tap = (unsigned char*)(smem + 27*TM*4);
    float2* sAd = (float2*)(smem + 27*TM*4 + 32);
    float*  sW  = (float*)(smem + 27*TM*4 + 32 + (size_t)TM*AROW*8);

    const int n = *nptr;
    const int base = blockIdx.x * TM;
    if (base >= n) return;

    const int tid = threadIdx.x;
    if (tid < 27) s_tap[tid] = 0;
    __syncthreads();

    for (int e = tid; e < 27*TM; e += THREADS) {
        int k = e / TM, r = e - k*TM;
        int idx = -1;
        int row = base + r;
        if (row < n) {
            int vox = ovox[row];
            int c = vox % O2; int t = vox / O2; int b = t % O1; int a = t / O1;
            int n0 = STRIDE*a + (k/9) - 1;
            int n1 = STRIDE*b + ((k/3)%3) - 1;
            int n2 = STRIDE*c + (k%3) - 1;
            if (n0 >= 0 && n0 < I0 && n1 >= 0 && n1 < I1 && n2 >= 0 && n2 < I2)
                idx = lut[(n0*I1 + n1)*I2 + n2];
        }
        s_idx[k*TM + r] = idx;
        if (idx >= 0) s_tap[k] = 1;
    }
    __syncthreads();

    const int rg = tid / CGn;
    const int cg = tid - rg*CGn;

    unsigned long long acc[4][4];
    #pragma unroll
    for (int r = 0; r < 4; r++)
        #pragma unroll
        for (int cp = 0; cp < 4; cp++) acc[r][cp] = 0ULL;

    for (int k = 0; k < 27; k++) {
        if (!s_tap[k]) continue;
        __syncthreads();
        for (int e = tid; e < TM*CIN; e += THREADS) {
            int r = e / CIN, ci = e - r*CIN;
            int id = s_idx[k*TM + r];
            float v = (id >= 0) ? fin[(size_t)id*CIN + ci] : 0.f;
            sAd[r*AROW + ci] = make_float2(v, v);
        }
        const float* Wk = W + (size_t)k*CIN*COUT;
        for (int ch = 0; ch < NCH; ch++) {
            __syncthreads();
            const float* Wc = Wk + (size_t)ch*CK*COUT;
            for (int e = tid; e < CK*COUT; e += THREADS)
                sW[e] = Wc[e];
            __syncthreads();
            const float2* aBase = sAd + ch*CK;
            #pragma unroll
            for (int s = 0; s < CK; s += 2) {
                ulonglong2 a2[4];
                #pragma unroll
                for (int r = 0; r < 4; r++)
                    a2[r] = *reinterpret_cast<const ulonglong2*>(aBase + (rg + r*RSTEP)*AROW + s);
                unsigned long long b0[4], b1[4];
                #pragma unroll
                for (int cp = 0; cp < 4; cp++) {
                    int co = 2*cg + (COUT/4)*cp;
                    b0[cp] = *reinterpret_cast<const unsigned long long*>(sW + s*COUT + co);
                    b1[cp] = *reinterpret_cast<const unsigned long long*>(sW + (s+1)*COUT + co);
                }
                #pragma unroll
                for (int r = 0; r < 4; r++) {
                    #pragma unroll
                    for (int cp = 0; cp < 4; cp++)
                        asm("fma.rn.f32x2 %0, %1, %2, %0;" : "+l"(acc[r][cp]) : "l"(a2[r].x), "l"(b0[cp]));
                    #pragma unroll
                    for (int cp = 0; cp < 4; cp++)
                        asm("fma.rn.f32x2 %0, %1, %2, %0;" : "+l"(acc[r][cp]) : "l"(a2[r].y), "l"(b1[cp]));
                }
            }
        }
    }

    #pragma unroll
    for (int cp = 0; cp < 4; cp++) {
        int co = 2*cg + (COUT/4)*cp;
        float scl0, sh0, scl1, sh1;
        if (bnp) {
            float g0 = bnp[co],   be0 = bnp[COUT+co],   mu0 = bnp[2*COUT+co],   vv0 = bnp[3*COUT+co];
            float g1 = bnp[co+1], be1 = bnp[COUT+co+1], mu1 = bnp[2*COUT+co+1], vv1 = bnp[3*COUT+co+1];
            scl0 = g0 * rsqrtf(vv0 + 1e-3f); sh0 = be0 - mu0*scl0;
            scl1 = g1 * rsqrtf(vv1 + 1e-3f); sh1 = be1 - mu1*scl1;
        } else {
            scl0 = 1.f; scl1 = 1.f;
            sh0 = bias ? bias[co]   : 0.f;
            sh1 = bias ? bias[co+1] : 0.f;
        }
        #pragma unroll
        for (int r = 0; r < 4; r++) {
            int row = base + rg + r*RSTEP;
            if (row >= n) continue;
            union { unsigned long long u; float2 f; } cv; cv.u = acc[r][cp];
            float2 v = cv.f;
            v.x = v.x*scl0 + sh0;
            v.y = v.y*scl1 + sh1;
            if (resid) {
                float2 rv = *reinterpret_cast<const float2*>(resid + (size_t)row*COUT + co);
                v.x += rv.x; v.y += rv.y;
            }
            if (do_relu) { v.x = fmaxf(v.x, 0.f); v.y = fmaxf(v.y, 0.f); }
            *reinterpret_cast<float2*>(fout + (size_t)row*COUT + co) = v;
        }
    }
}

// ================= tcgen05 TF32 conv =================
__device__ __forceinline__ uint32_t swz128(uint32_t x) { return x ^ ((x >> 3) & 0x70); }

__device__ __forceinline__ uint32_t smem_u32(const void* p) {
    uint32_t a;
    asm("{ .reg .u64 t; cvta.to.shared.u64 t, %1; cvt.u32.u64 %0, t; }" : "=r"(a) : "l"(p));
    return a;
}

// SW128 K-major descriptor: layout=2, version=1, SBO=64, LBO=1
#define DESC_BASE_SW128 ((2ull<<61)|(1ull<<46)|(64ull<<32)|(1ull<<16))
__device__ __forceinline__ uint64_t mk_desc(uint32_t addr) {
    return DESC_BASE_SW128 | ((uint64_t)(addr >> 4) & 0x3FFF);
}

// idesc: dtype F32(1)@4, atype TF32(2)@7, btype TF32(2)@10, N=128 -> 16@17, M=128 -> 8@24
#define IDESC_TF32 ((1u<<4)|(2u<<7)|(2u<<10)|(16u<<17)|(8u<<24))

#if TC_PATH
__device__ __forceinline__ void mma_tf32_ss(uint32_t d, uint64_t a, uint64_t b,
                                            uint32_t idesc, uint32_t en) {
    asm volatile(
        "{\n\t"
        ".reg .pred p;\n\t"
        "setp.ne.u32 p, %5, 0;\n\t"
        "tcgen05.mma.cta_group::1.kind::tf32 [%0], %1, %2, %3, {%4, %4, %4, %4}, p;\n\t"
        "}"
        :: "r"(d), "l"(a), "l"(b), "r"(idesc), "r"(0u), "r"(en) : "memory");
}

__device__ __forceinline__ void ldtm_x32(uint32_t* r, uint32_t addr) {
    asm volatile(
        "tcgen05.ld.sync.aligned.32x32b.x32.b32 "
        "{%0, %1, %2, %3, %4, %5, %6, %7, "
        " %8, %9, %10, %11, %12, %13, %14, %15, "
        " %16, %17, %18, %19, %20, %21, %22, %23, "
        " %24, %25, %26, %27, %28, %29, %30, %31}, [%32];"
        : "=r"(r[0]),  "=r"(r[1]),  "=r"(r[2]),  "=r"(r[3]),
          "=r"(r[4]),  "=r"(r[5]),  "=r"(r[6]),  "=r"(r[7]),
          "=r"(r[8]),  "=r"(r[9]),  "=r"(r[10]), "=r"(r[11]),
          "=r"(r[12]), "=r"(r[13]), "=r"(r[14]), "=r"(r[15]),
          "=r"(r[16]), "=r"(r[17]), "=r"(r[18]), "=r"(r[19]),
          "=r"(r[20]), "=r"(r[21]), "=r"(r[22]), "=r"(r[23]),
          "=r"(r[24]), "=r"(r[25]), "=r"(r[26]), "=r"(r[27]),
          "=r"(r[28]), "=r"(r[29]), "=r"(r[30]), "=r"(r[31])
        : "r"(addr));
}
#endif

__device__ __forceinline__ void cp16(uint32_t dst, const void* src, int sz) {
    asm volatile("cp.async.cg.shared.global [%0], [%1], 16, %2;"
                 :: "r"(dst), "l"(src), "r"(sz));
}

__device__ __forceinline__ void mbar_wait(uint32_t mbar, int parity) {
    asm volatile(
        "{\n\t"
        ".reg .pred P;\n\t"
        "LW%=:\n\t"
        "mbarrier.try_wait.parity.acquire.cta.shared::cta.b64 P, [%0], %1, 0x989680;\n\t"
        "@!P bra LW%=;\n\t"
        "}" :: "r"(mbar), "r"(parity) : "memory");
}

// prep: transpose+swizzle weights W[27][CIN][128] -> image [27][CIN/32][16KB swizzled]
template<int CIN>
__global__ void prep_w(const float* __restrict__ w, float* __restrict__ dst)
{
    int i = blockIdx.x*blockDim.x + threadIdx.x;
    if (i >= 27*CIN*128) return;
    int co = i & 127; int t = i >> 7; int ci = t % CIN; int k = t / CIN;
    float v = w[((size_t)k*CIN + ci)*128 + co];
    int chunk = ci >> 5, col = ci & 31;
    uint32_t boff = swz128((uint32_t)(co*128 + col*4));
    dst[(size_t)k*(CIN/32)*4096 + (size_t)chunk*4096 + (boff >> 2)] = v;
}

// TF32 tensor-core sparse conv: M=128 rows/block, N=128, K=CINC*32 per tap, 27 taps in TMEM.
template<int CINC, int STRIDE>
__global__ void __launch_bounds__(256) convtc_kernel(
    const float* __restrict__ fin,
    const int* __restrict__ ovox,
    const int* __restrict__ nptr,
    const int* __restrict__ lut,
    int O1, int O2, int I0, int I1, int I2,
    const float* __restrict__ wT,   // prepped image: [27][CINC][4096 floats]
    float* __restrict__ fout,
    const float* __restrict__ bnp,
    const float* __restrict__ bias,
    const float* __restrict__ resid,
    int do_relu)
{
    extern __shared__ char smem[];
    const int n = *nptr;
    const int base = blockIdx.x * 128;
    if (base >= n) return;

    const uint32_t sb = smem_u32(smem);
    const int tid = threadIdx.x;
    const int wid = tid >> 5, lane = tid & 31;

    const uint32_t tptr = sb + 0;
    const uint32_t mbar = sb + 8;
    unsigned char* s_tap = (unsigned char*)(smem + 16);
    float* s_scl = (float*)(smem + 64);
    float* s_sh  = (float*)(smem + 576);
    int*   s_idx = (int*)(smem + 1088);           // 27*128 ints -> ends at 14912
    const uint32_t Aabs = (sb + 14912 + 1023) & ~1023u;
    const uint32_t Babs = Aabs + CINC*16384;

#if TC_PATH
    if (wid == 0) {
        asm volatile("tcgen05.alloc.cta_group::1.sync.aligned.shared::cta.b32 [%0], %1;"
                     :: "r"(tptr), "r"(128) : "memory");
        asm volatile("tcgen05.relinquish_alloc_permit.cta_group::1.sync.aligned;");
    }
    if (tid == 0)
        asm volatile("mbarrier.init.shared.b64 [%0], %1;" :: "r"(mbar), "r"(1) : "memory");
#endif
    if (tid < 27) s_tap[tid] = 0;
    if (tid < 128) {
        float scl, sh;
        if (bnp) {
            float g = bnp[tid], be = bnp[128+tid], mu = bnp[256+tid], vv = bnp[384+tid];
            scl = g * rsqrtf(vv + 1e-3f); sh = be - mu*scl;
        } else { scl = 1.f; sh = bias ? bias[tid] : 0.f; }
        s_scl[tid] = scl; s_sh[tid] = sh;
    }
    __syncthreads();

    for (int e = tid; e < 27*128; e += 256) {
        int k = e >> 7, r = e & 127;
        int idx = -1;
        int row = base + r;
        if (row < n) {
            int vox = ovox[row];
            int c = vox % O2; int t = vox / O2; int b = t % O1; int a = t / O1;
            int n0 = STRIDE*a + (k/9) - 1;
            int n1 = STRIDE*b + ((k/3)%3) - 1;
            int n2 = STRIDE*c + (k%3) - 1;
            if (n0 >= 0 && n0 < I0 && n1 >= 0 && n1 < I1 && n2 >= 0 && n2 < I2)
                idx = lut[(n0*I1 + n1)*I2 + n2];
        }
        s_idx[e] = idx;
        if (idx >= 0) s_tap[k] = 1;
    }
    __syncthreads();

#if TC_PATH
    uint32_t tmem;
    asm volatile("ld.shared.b32 %0, [%1];" : "=r"(tmem) : "r"(tptr));

    int phase = 0;
    uint32_t en = 0;   // first MMA overwrites D
    for (int k = 0; k < 27; k++) {
        if (!s_tap[k]) continue;
        // stage A: 128 rows x CINC chunks x 8 x 16B (zero-fill missing neighbors)
        const int* idxk = s_idx + (k << 7);
        const int NA = 128 * 8 * CINC;
        for (int e = tid; e < NA; e += 256) {
            int row = e / (8*CINC);
            int piece = e - row*8*CINC;
            int chunk = piece >> 3, j = piece & 7;
            int id = idxk[row];
            const float* src = fin + (size_t)(id < 0 ? 0 : id)*(CINC*32) + chunk*32 + j*4;
            uint32_t dst = Aabs + chunk*16384 + swz128((uint32_t)(row*128 + j*16));
            cp16(dst, src, id >= 0 ? 16 : 0);
        }
        // stage B: contiguous prepped image, CINC*4096 floats = CINC*1024 x 16B
        const float* wk = wT + (size_t)k*CINC*4096;
        for (int e = tid; e < CINC*1024; e += 256)
            cp16(Babs + e*16, wk + e*4, 16);
        asm volatile("cp.async.commit_group;");
        asm volatile("cp.async.wait_group 0;");
        __syncthreads();
        if (tid == 0) {
            asm volatile("fence.proxy.async.shared::cta;" ::: "memory");
            #pragma unroll
            for (int c = 0; c < CINC; c++) {
                uint64_t ad = mk_desc(Aabs + c*16384);
                uint64_t bd = mk_desc(Babs + c*16384);
                #pragma unroll
                for (int kc = 0; kc < 4; kc++) {
                    mma_tf32_ss(tmem, ad + 2*kc, bd + 2*kc, IDESC_TF32, en);
                    en = 1;
                }
            }
            asm volatile("tcgen05.commit.cta_group::1.mbarrier::arrive::one.shared::cluster.b64 [%0];"
                         :: "r"(mbar) : "memory");
        }
        mbar_wait(mbar, phase);
        phase ^= 1;
    }
    asm volatile("tcgen05.fence::after_thread_sync;" ::: "memory");

    // epilogue: warp w -> TMEM lanes (w%4)*32.., cols (w/4)*64..+63
    {
        int rloc = (wid & 3)*32 + lane;
        int row  = base + rloc;
        int c0   = (wid >> 2)*64;
        uint32_t d[64];
        ldtm_x32(d,      tmem + c0);
        ldtm_x32(d + 32, tmem + c0 + 32);
        asm volatile("tcgen05.wait::ld.sync.aligned;" ::: "memory");
        if (row < n) {
            #pragma unroll
            for (int g4 = 0; g4 < 16; g4++) {
                int c = c0 + g4*4;
                float4 v;
                v.x = __uint_as_float(d[g4*4+0])*s_scl[c+0] + s_sh[c+0];
                v.y = __uint_as_float(d[g4*4+1])*s_scl[c+1] + s_sh[c+1];
                v.z = __uint_as_float(d[g4*4+2])*s_scl[c+2] + s_sh[c+2];
                v.w = __uint_as_float(d[g4*4+3])*s_scl[c+3] + s_sh[c+3];
                if (resid) {
                    float4 rv = *reinterpret_cast<const float4*>(resid + (size_t)row*128 + c);
                    v.x += rv.x; v.y += rv.y; v.z += rv.z; v.w += rv.w;
                }
                if (do_relu) {
                    v.x = fmaxf(v.x, 0.f); v.y = fmaxf(v.y, 0.f);
                    v.z = fmaxf(v.z, 0.f); v.w = fmaxf(v.w, 0.f);
                }
                *reinterpret_cast<float4*>(fout + (size_t)row*128 + c) = v;
            }
        }
    }
    __syncthreads();
    if (tid == 0)
        asm volatile("mbarrier.inval.shared.b64 [%0];" :: "r"(mbar) : "memory");
    __syncthreads();
    if (wid == 0)
        asm volatile("tcgen05.dealloc.cta_group::1.sync.aligned.b32 %0, %1;" :: "r"(tmem), "r"(128));
#else
    // scalar fallback for the generic compute_103 PTX pass (never executed —
    // the sm_103a cubin is always preferred — but kept correct regardless).
    for (int o = tid; o < 128*128; o += 256) {
        int r = o >> 7, co = o & 127;
        int row = base + r;
        if (row >= n) continue;
        float acc = 0.f;
        for (int k = 0; k < 27; k++) {
            int id = s_idx[(k << 7) + r];
            if (id < 0) continue;
            const float* f = fin + (size_t)id*(CINC*32);
            const float* w = wT + (size_t)k*CINC*4096;
            for (int ci = 0; ci < CINC*32; ci++) {
                int chunk = ci >> 5, col = ci & 31;
                uint32_t boff = swz128((uint32_t)(co*128 + col*4));
                acc += f[ci] * w[(size_t)chunk*4096 + (boff >> 2)];
            }
        }
        float v = acc*s_scl[co] + s_sh[co];
        if (resid) v += resid[(size_t)row*128 + co];
        if (do_relu) v = fmaxf(v, 0.f);
        fout[(size_t)row*128 + co] = v;
    }
#endif
}

// ---------------- final GN(16) + relu + transposed dense scatter ----------------
__global__ void finalize_kernel(const float* __restrict__ gg, const float* __restrict__ gb,
                                float* __restrict__ out)
{
    int warp = (blockIdx.x*blockDim.x + threadIdx.x) >> 5;
    int lane = threadIdx.x & 31;
    if (warp >= g_cnt[1]) return;
    int row = warp;
    float4 fv = *reinterpret_cast<const float4*>(&g_f2b[(size_t)row*128 + lane*4]);
    float f[4] = {fv.x, fv.y, fv.z, fv.w};
    float s = f[0]+f[1]+f[2]+f[3];
    s += __shfl_xor_sync(0xffffffff, s, 1);
    float m = s * 0.125f;
    float q = 0.f;
    #pragma unroll
    for (int jj = 0; jj < 4; jj++) { float d = f[jj]-m; q += d*d; }
    q += __shfl_xor_sync(0xffffffff, q, 1);
    float rr = rsqrtf(q*0.125f + 1e-5f);
    int vox = g_oc2[row];
    int a2 = vox % S2C; int t = vox / S2C; int a1 = t % S2B; int a0 = t / S2B;
    #pragma unroll
    for (int jj = 0; jj < 4; jj++) {
        int c = lane*4 + jj;
        float y = (f[jj]-m)*rr*gg[c] + gb[c];
        y = fmaxf(y, 0.f);
        out[(((size_t)c*S2C + a2)*S2B + a1)*S2A + a0] = y;
    }
}

static inline size_t convx_smem(int TM, int CIN, int COUT) {
    int CK = (CIN < 32) ? CIN : 32;
    return (size_t)27*TM*4 + 32 + (size_t)TM*(CIN+2)*8 + (size_t)CK*COUT*4;
}

// ---------------- launch ----------------
extern "C" void kernel_launch(void* const* d_in, const int* in_sizes, int n_in,
                              void* d_out, int out_size)
{
    int has_bs = (n_in < 3 || in_sizes[2] == 1) ? 1 : 0;
    #define GI(i) ((const float*)d_in[((i) >= 2 && !has_bs) ? (i)-1 : (i)])

    const float* vf    = (const float*)d_in[0];
    const int*   coors = (const int*)d_in[1];
    const float* ele_t = GI(3);
    const float* azi_t = GI(4);
    const float* wq = GI(5),  *bq = GI(6);
    const float* wk = GI(7),  *bk = GI(8);
    const float* wv = GI(9),  *bv = GI(10);
    const float* w_in = GI(11), *b_in = GI(12), *gin_g = GI(13), *gin_b = GI(14);
    const float* w_d1 = GI(15), *bn_d1 = GI(16);
    const float* w_r1 = GI(17), *bn_r1 = GI(18);
    const float* w_d2 = GI(19), *bn_d2 = GI(20);
    const float* w_r2 = GI(21), *bn_r2 = GI(22);
    const float* w_out = GI(23), *b_out = GI(24), *gout_g = GI(25), *gout_b = GI(26);

    void* p;
    cudaGetSymbolAddress(&p, g_f0);   float* f0p  = (float*)p;
    cudaGetSymbolAddress(&p, g_f1a);  float* f1ap = (float*)p;
    cudaGetSymbolAddress(&p, g_f1b);  float* f1bp = (float*)p;
    cudaGetSymbolAddress(&p, g_f2a);  float* f2ap = (float*)p;
    cudaGetSymbolAddress(&p, g_f2b);  float* f2bp = (float*)p;
    cudaGetSymbolAddress(&p, g_lut0); int* lut0p = (int*)p;
    cudaGetSymbolAddress(&p, g_lut1); int* lut1p = (int*)p;
    cudaGetSymbolAddress(&p, g_lut2); int* lut2p = (int*)p;
    cudaGetSymbolAddress(&p, g_oc1);  int* oc1p  = (int*)p;
    cudaGetSymbolAddress(&p, g_oc2);  int* oc2p  = (int*)p;
    cudaGetSymbolAddress(&p, g_cnt);  int* cntp  = (int*)p;
    cudaGetSymbolAddress(&p, g_om1);  unsigned char* om1p = (unsigned char*)p;
    cudaGetSymbolAddress(&p, g_om2);  unsigned char* om2p = (unsigned char*)p;
    cudaGetSymbolAddress(&p, g_wT);   float* wTp = (float*)p;

    size_t sm_d1  = convx_smem(128, 16, 32);
    size_t sm_r1  = convx_smem(128, 32, 32);
    cudaFuncSetAttribute((const void*)convx_kernel<16,32,2,128>, cudaFuncAttributeMaxDynamicSharedMemorySize, (int)sm_d1);
    cudaFuncSetAttribute((const void*)convx_kernel<32,32,1,128>, cudaFuncAttributeMaxDynamicSharedMemorySize, (int)sm_r1);

    const size_t sm_tc4 = 14912 + 1024 + 4*16384 + 4*16384;  // ~147KB
    const size_t sm_tc1 = 14912 + 1024 + 16384 + 16384;      // ~48.7KB
    cudaFuncSetAttribute((const void*)convtc_kernel<4,1>, cudaFuncAttributeMaxDynamicSharedMemorySize, (int)sm_tc4);
    cudaFuncSetAttribute((const void*)convtc_kernel<1,2>, cudaFuncAttributeMaxDynamicSharedMemorySize, (int)sm_tc1);

    cudaMemsetAsync(lut0p, 0xFF, sizeof(int)*(size_t)L0VOX);
    cudaMemsetAsync(lut1p, 0xFF, sizeof(int)*(size_t)L1VOX);
    cudaMemsetAsync(lut2p, 0xFF, sizeof(int)*(size_t)L2VOX);
    cudaMemsetAsync(om1p, 0, (size_t)L1VOX);
    cudaMemsetAsync(om2p, 0, (size_t)L2VOX);
    cudaMemsetAsync(cntp, 0, 2*sizeof(int));
    cudaMemsetAsync(d_out, 0, (size_t)out_size*sizeof(float));

    const int WR2 = 27*128*128;
    // prep tensor-core weight images (independent of data pipeline)
    prep_w<32><<<(27*32*128+255)/256, 256>>>(w_d2, wTp + 0*WSLOT);
    prep_w<128><<<(27*128*128+255)/256, 256>>>(w_r2 + 0*WR2, wTp + 1*WSLOT);
    prep_w<128><<<(27*128*128+255)/256, 256>>>(w_r2 + 1*WR2, wTp + 2*WSLOT);
    prep_w<128><<<(27*128*128+255)/256, 256>>>(w_r2 + 2*WR2, wTp + 3*WSLOT);
    prep_w<128><<<(27*128*128+255)/256, 256>>>(w_r2 + 3*WR2, wTp + 4*WSLOT);
    prep_w<128><<<(27*128*128+255)/256, 256>>>(w_out,        wTp + 5*WSLOT);

    attn_kernel<<<NROW, 256>>>(vf, coors, ele_t, azi_t, wq, bq, wk, bk, wv, bv);
    point_kernel<<<(NPTS+255)/256, 256>>>(coors, w_in, b_in, gin_g, gin_b);
    compact_kernel<<<(L1VOX+255)/256, 256>>>(om1p, lut1p, oc1p, cntp, L1VOX, CAP1);
    mark2_kernel<<<(CAP1+255)/256, 256>>>();
    compact_kernel<<<(L2VOX+255)/256, 256>>>(om2p, lut2p, oc2p, cntp+1, L2VOX, CAP2);

    const int G1 = (CAP1+127)/128;
    const int GT = (CAP2+127)/128;
    const int T32 = (128/4)*(32/8);
    const int WR1 = 27*32*32;

    // level-1: scalar f32x2
    convx_kernel<16,32,2,128><<<G1,T32,sm_d1>>>(f0p, oc1p, cntp, lut0p, S1B, S1C, S0A, S0B, S0C,
                                                w_d1, f1ap, bn_d1, nullptr, nullptr, 1);
    convx_kernel<32,32,1,128><<<G1,T32,sm_r1>>>(f1ap, oc1p, cntp, lut1p, S1B, S1C, S1A, S1B, S1C,
                                                w_r1 + 0*WR1, f1bp, bn_r1 + 0*128, nullptr, nullptr, 1);
    convx_kernel<32,32,1,128><<<G1,T32,sm_r1>>>(f1bp, oc1p, cntp, lut1p, S1B, S1C, S1A, S1B, S1C,
                                                w_r1 + 1*WR1, f1ap, bn_r1 + 1*128, nullptr, f1ap, 1);
    convx_kernel<32,32,1,128><<<G1,T32,sm_r1>>>(f1ap, oc1p, cntp, lut1p, S1B, S1C, S1A, S1B, S1C,
                                                w_r1 + 2*WR1, f1bp, bn_r1 + 2*128, nullptr, nullptr, 1);
    convx_kernel<32,32,1,128><<<G1,T32,sm_r1>>>(f1bp, oc1p, cntp, lut1p, S1B, S1C, S1A, S1B, S1C,
                                                w_r1 + 3*WR1, f1ap, bn_r1 + 3*128, nullptr, f1ap, 1);

    // level-2: tcgen05 TF32
    convtc_kernel<1,2><<<GT,256,sm_tc1>>>(f1ap, oc2p, cntp+1, lut1p, S2B, S2C, S1A, S1B, S1C,
                                          wTp + 0*WSLOT, f2ap, bn_d2, nullptr, nullptr, 1);
    convtc_kernel<4,1><<<GT,256,sm_tc4>>>(f2ap, oc2p, cntp+1, lut2p, S2B, S2C, S2A, S2B, S2C,
                                          wTp + 1*WSLOT, f2bp, bn_r2 + 0*512, nullptr, nullptr, 1);
    convtc_kernel<4,1><<<GT,256,sm_tc4>>>(f2bp, oc2p, cntp+1, lut2p, S2B, S2C, S2A, S2B, S2C,
                                          wTp + 2*WSLOT, f2ap, bn_r2 + 1*512, nullptr, f2ap, 1);
    convtc_kernel<4,1><<<GT,256,sm_tc4>>>(f2ap, oc2p, cntp+1, lut2p, S2B, S2C, S2A, S2B, S2C,
                                          wTp + 3*WSLOT, f2bp, bn_r2 + 2*512, nullptr, nullptr, 1);
    convtc_kernel<4,1><<<GT,256,sm_tc4>>>(f2bp, oc2p, cntp+1, lut2p, S2B, S2C, S2A, S2B, S2C,
                                          wTp + 4*WSLOT, f2ap, bn_r2 + 3*512, nullptr, f2ap, 1);
    convtc_kernel<4,1><<<GT,256,sm_tc4>>>(f2ap, oc2p, cntp+1, lut2p, S2B, S2C, S2A, S2B, S2C,
                                          wTp + 5*WSLOT, f2bp, nullptr, b_out, nullptr, 0);

    finalize_kernel<<<(CAP2+7)/8, 256>>>(gout_g, gout_b, (float*)d_out);
}